// round 3
// baseline (speedup 1.0000x reference)
#include <cuda_runtime.h>

#define TSEQ 2048
#define BATCH 64
#define HID 256
#define NBLOCKS 128
#define NTHREADS 256

// shared memory layout (in floats)
#define SM_W    0        // sWt[k][16], KT<=768 -> 12288 floats
#define SM_IN   12288    // sIn4[64][33] float4 = 8448 floats (padded rows of 132 floats)
#define SM_ZB   20736    // zb[16][65] = 1040
#define SM_HB   21776    // hb[4][65]  = 260
#define SM_B    22036    // bias[16]
#define SM_LEN  22052    // int lens[64]
#define SMEM_FLOATS 22116
#define SMEM_BYTES (SMEM_FLOATS * 4)

#define OUT_LH 67108864UL          // T*B*2H
#define LHN    65536UL             // 4*B*H

// scratch (device statics are the sanctioned no-alloc path)
__device__ float g_hs0f[(size_t)TSEQ * BATCH * HID];
__device__ float g_hs0b[(size_t)TSEQ * BATCH * HID];
__device__ float g_h[2][2][BATCH * HID];   // [parity][dir][b*H + j]
__device__ unsigned g_sync[8];             // [0..2]=counters (fwd,bwd,all), [4..6]=generations

struct Params {
    const float* __restrict__ x;
    const int*   __restrict__ len;
    const float* __restrict__ w[16];
    float*       __restrict__ out;
};

__device__ __forceinline__ void gbar(int idx, unsigned n, unsigned target) {
    __syncthreads();
    if (threadIdx.x == 0) {
        unsigned old;
        asm volatile("atom.add.acq_rel.gpu.global.u32 %0, [%1], %2;"
                     : "=r"(old) : "l"(&g_sync[idx]), "r"(1u) : "memory");
        if (old == n - 1) {
            g_sync[idx] = 0;  // ordered before the release store below
            asm volatile("st.release.gpu.global.u32 [%0], %1;"
                         :: "l"(&g_sync[4 + idx]), "r"(target) : "memory");
        } else {
            unsigned v;
            do {
                asm volatile("ld.acquire.gpu.global.u32 %0, [%1];"
                             : "=r"(v) : "l"(&g_sync[4 + idx]) : "memory");
            } while (v < target);
        }
    }
    __syncthreads();
}

__device__ __forceinline__ float sigf(float x) { return 1.f / (1.f + __expf(-x)); }

__global__ void __launch_bounds__(NTHREADS, 1)
lstm_kernel(Params p)
{
    extern __shared__ float sm[];
    float*  sWt  = sm + SM_W;                 // [k][16]
    float4* sIn4 = (float4*)(sm + SM_IN);     // [b][33] float4
    float*  sInf = sm + SM_IN;                // [b][132] floats
    float*  zb   = sm + SM_ZB;                // [row][65]
    float*  hb   = sm + SM_HB;                // [jloc][65]
    float*  sB   = sm + SM_B;                 // [16]
    int*    sLen = (int*)(sm + SM_LEN);       // [64]

    const int tid = threadIdx.x;
    const int dir = blockIdx.x >> 6;          // 0 = fwd, 1 = bwd
    const int j0  = (blockIdx.x & 63) << 2;   // this block's 4 hidden units
    const int rq  = tid & 3;                  // GEMM: gate index (rows rq*4..rq*4+3)
    const int gb  = tid >> 2;                 // GEMM: batch
    const int uj  = tid >> 6;                 // update: jloc
    const int ub  = tid & 63;                 // update: batch

    if (tid < BATCH) sLen[tid] = p.len[tid];

    unsigned ts = 0, ta = 0;
    float4 rbuf[8];

    for (int layer = 0; layer < 2; ++layer) {
        const int Din = layer ? 512 : 256;
        const int KT  = Din + HID;
        const int NC  = KT >> 7;              // 4 or 6 chunks of 128 k
        const float* wih = p.w[layer * 8 + dir * 4 + 0];
        const float* whh = p.w[layer * 8 + dir * 4 + 1];
        const float* bih = p.w[layer * 8 + dir * 4 + 2];
        const float* bhh = p.w[layer * 8 + dir * 4 + 3];

        // load weights: sWt[k][row], row = gate*4 + jloc, global row = gate*256 + j0 + jloc
        for (int r = 0; r < 16; ++r) {
            int grow = ((r >> 2) << 8) + j0 + (r & 3);
            const float* wi = wih + (size_t)grow * Din;
            const float* wh = whh + (size_t)grow * HID;
            for (int k = tid; k < KT; k += NTHREADS)
                sWt[k * 16 + r] = (k < Din) ? wi[k] : wh[k - Din];
        }
        if (tid < 16) {
            int grow = ((tid >> 2) << 8) + j0 + (tid & 3);
            sB[tid] = bih[grow] + bhh[grow];
        }
        // zero h (parity 0) for this block's j-slice
        g_h[0][dir][(tid & 63) * HID + j0 + (tid >> 6)] = 0.f;
        float creg = 0.f;

        gbar(2, NBLOCKS, ++ta);   // full barrier: h zeros + (layer 1) hs0 history visible

        for (int s = 0; s < TSEQ; ++s) {
            const int par = s & 1;
            const int t = dir ? (TSEQ - 1 - s) : s;   // fwd: t, bwd: t'

            // ---- stage one chunk into registers ----
            auto stage = [&](int c) {
                const int loc  = (c & 1) << 7;           // local k offset within 256-wide source
                const bool isH = (c >= NC - 2);
                const bool isB = (layer == 1) && ((c >> 1) == 1);
                const float* base = isH ? (const float*)&g_h[par][dir][0]
                                  : (isB ? (const float*)g_hs0b
                                  : (layer ? (const float*)g_hs0f : p.x));
#pragma unroll
                for (int i = 0; i < 8; ++i) {
                    int f = (i << 8) + tid;
                    int b = f >> 5, kq = f & 31;
                    if (isH) {
                        rbuf[i] = __ldcg((const float4*)(base + b * HID + loc) + kq);
                    } else {
                        int lb = sLen[b];
                        // gather time index per example:
                        //  x / hs0f : fwd -> t        ; bwd -> (t' + len) mod T
                        //  hs0b     : fwd -> (t+T-len); bwd -> t'
                        int tb = isB ? (dir ? t : t + TSEQ - lb)
                                     : (dir ? t + lb : t);
                        if (tb >= TSEQ) tb -= TSEQ;
                        rbuf[i] = __ldcg((const float4*)(base + ((size_t)tb * BATCH + b) * HID + loc) + kq);
                    }
                }
            };
            auto commit = [&]() {
#pragma unroll
                for (int i = 0; i < 8; ++i) {
                    int f = (i << 8) + tid;
                    sIn4[(f >> 5) * 33 + (f & 31)] = rbuf[i];
                }
            };

            float a0 = sB[(rq << 2) + 0], a1 = sB[(rq << 2) + 1];
            float a2 = sB[(rq << 2) + 2], a3 = sB[(rq << 2) + 3];

            stage(0);
            for (int c = 0; c < NC; ++c) {
                commit();
                __syncthreads();
                if (c + 1 < NC) stage(c + 1);   // prefetch next chunk during compute
                const float4* wp = (const float4*)sWt + (c << 9) + rq;  // (k*4 + rq)
                const float*  ip = sInf + gb * 132;
#pragma unroll 8
                for (int kk = 0; kk < 128; ++kk) {
                    float4 w = wp[kk << 2];
                    float iv = ip[kk];
                    a0 = fmaf(w.x, iv, a0);
                    a1 = fmaf(w.y, iv, a1);
                    a2 = fmaf(w.z, iv, a2);
                    a3 = fmaf(w.w, iv, a3);
                }
                __syncthreads();
            }

            zb[((rq << 2) + 0) * 65 + gb] = a0;
            zb[((rq << 2) + 1) * 65 + gb] = a1;
            zb[((rq << 2) + 2) * 65 + gb] = a2;
            zb[((rq << 2) + 3) * 65 + gb] = a3;
            __syncthreads();

            // ---- cell update: thread owns (uj, ub), c stays in register ----
            {
                float zi = zb[(0  + uj) * 65 + ub];
                float zf = zb[(4  + uj) * 65 + ub];
                float zg = zb[(8  + uj) * 65 + ub];
                float zo = zb[(12 + uj) * 65 + ub];
                float ig = sigf(zi), fg = sigf(zf), gg = tanhf(zg), og = sigf(zo);
                creg = fg * creg + ig * gg;
                float h = og * tanhf(creg);
                hb[uj * 65 + ub] = h;
                int lb = sLen[ub];
                bool trig = dir ? (t == TSEQ - lb) : (t == lb - 1);
                if (trig) {   // final valid state for this example
                    size_t o = OUT_LH + ((size_t)(layer * 2 + dir) * BATCH + ub) * HID + j0 + uj;
                    p.out[o] = h;
                    p.out[o + LHN] = creg;
                }
            }
            __syncthreads();

            // ---- transpose write (j fastest for 16B-coalesced segments) ----
            {
                int j = tid & 3, b = tid >> 2;
                float hv = hb[j * 65 + b];
                g_h[par ^ 1][dir][b * HID + j0 + j] = hv;
                if (layer == 0) {
                    float* hs = dir ? g_hs0b : g_hs0f;
                    hs[((size_t)t * BATCH + b) * HID + j0 + j] = hv;
                } else {
                    int lb = sLen[b];
                    int tm = t, col = j0 + j;
                    if (dir) { tm = t + lb; if (tm >= TSEQ) tm -= TSEQ; col += HID; }
                    p.out[((size_t)tm * BATCH + b) * (2 * HID) + col] = (tm < lb) ? hv : 0.f;
                }
            }

            gbar(dir, 64, ++ts);   // per-direction step barrier (64 blocks)
        }
    }
}

extern "C" void kernel_launch(void* const* d_in, const int* in_sizes, int n_in,
                              void* d_out, int out_size) {
    Params P;
    P.x   = (const float*)d_in[0];
    P.len = (const int*)d_in[1];
    for (int i = 0; i < 16; ++i) P.w[i] = (const float*)d_in[2 + i];
    P.out = (float*)d_out;

    void* sa = nullptr;
    cudaGetSymbolAddress(&sa, g_sync);
    cudaMemsetAsync(sa, 0, 8 * sizeof(unsigned));   // reset barrier state every launch

    cudaFuncSetAttribute(lstm_kernel, cudaFuncAttributeMaxDynamicSharedMemorySize, SMEM_BYTES);
    lstm_kernel<<<NBLOCKS, NTHREADS, SMEM_BYTES>>>(P);
}

// round 4
// speedup vs baseline: 1.0497x; 1.0497x over previous
#include <cuda_runtime.h>

#define TSEQ 2048
#define BATCH 64
#define HID 256
#define NBLOCKS 128
#define NTHREADS 256
#define MTOT (TSEQ * BATCH)          // 131072 rows

#define OUT_LH 67108864UL            // T*B*2H
#define LHN    65536UL               // 4*B*H

// ---- scratch (device statics are the sanctioned no-alloc path) ----
__device__ float g_zin[4][(size_t)MTOT * 1024];   // precomputed input projections
__device__ float g_hs0f[(size_t)MTOT * HID];
__device__ float g_hs0b[(size_t)MTOT * HID];
__device__ float g_h[2][2][BATCH * HID];          // [parity][dir][b*H + j]
__device__ unsigned g_sync[8];                    // [0,1]=counters(fwd,bwd) [4,5]=gens

struct Params {
    const float* __restrict__ x;
    const int*   __restrict__ len;
    const float* __restrict__ w[16];
    float*       __restrict__ out;
};

// ---------------- scan-phase shared memory layout (floats) ----------------
// sWt  [256][16]           : 0      .. 4096
// sHb  [64][276] (gap@128) : 4096   .. 21760
// zp   [2][16][66]         : 21760  .. 23872
// hb   [4][65]             : 23872  .. 24132
// sB   [16]                : 24132  .. 24148
// sLen [64] ints           : 24148  .. 24212
#define SM_HB   4096
#define SM_ZP   21760
#define SM_HBUF 23872
#define SM_B    24132
#define SM_LEN  24148
#define SMEM_FLOATS 24212
#define SMEM_BYTES (SMEM_FLOATS * 4)

__device__ __forceinline__ void gbar(int idx, unsigned n, unsigned target) {
    __syncthreads();
    if (threadIdx.x == 0) {
        unsigned old;
        asm volatile("atom.add.acq_rel.gpu.global.u32 %0, [%1], %2;"
                     : "=r"(old) : "l"(&g_sync[idx]), "r"(1u) : "memory");
        if (old == n - 1) {
            g_sync[idx] = 0;
            asm volatile("st.release.gpu.global.u32 [%0], %1;"
                         :: "l"(&g_sync[4 + idx]), "r"(target) : "memory");
        } else {
            unsigned v;
            do {
                asm volatile("ld.acquire.gpu.global.u32 %0, [%1];"
                             : "=r"(v) : "l"(&g_sync[4 + idx]) : "memory");
            } while (v < target);
        }
    }
    __syncthreads();
}

__device__ __forceinline__ float sigf(float x) {
    return __fdividef(1.f, 1.f + __expf(-x));
}

// =======================================================================
// Bulk GEMM: C[M=131072,1024] = A[M,256] @ W[1024, ldw(first 256 cols)]^T
// tile 128x128, 256 threads, 8x8 per thread, BK=16 double-buffered
// =======================================================================
__global__ void __launch_bounds__(256, 2)
gemm_k256(const float* __restrict__ A, const float* __restrict__ W, int ldw,
          float* __restrict__ C)
{
    __shared__ float sA[2][16][132];
    __shared__ float sB[2][16][132];
    const int tid = threadIdx.x;
    const int m0 = blockIdx.y << 7;
    const int n0 = blockIdx.x << 7;
    const int tx = tid & 15, ty = tid >> 4;
    const int lr = tid >> 2;               // 0..63
    const int lk = (tid & 3) << 2;         // 0,4,8,12

    const float* Ap0 = A + (size_t)(m0 + lr) * 256 + lk;
    const float* Ap1 = Ap0 + (size_t)64 * 256;
    const float* Wp0 = W + (size_t)(n0 + lr) * ldw + lk;
    const float* Wp1 = Wp0 + (size_t)64 * ldw;

    float acc[8][8];
#pragma unroll
    for (int i = 0; i < 8; ++i)
#pragma unroll
        for (int j = 0; j < 8; ++j) acc[i][j] = 0.f;

    float4 ra0, ra1, rb0, rb1;

#define GLOAD(kb) do { int k0_ = (kb) << 4;                         \
        ra0 = __ldg((const float4*)(Ap0 + k0_));                    \
        ra1 = __ldg((const float4*)(Ap1 + k0_));                    \
        rb0 = __ldg((const float4*)(Wp0 + k0_));                    \
        rb1 = __ldg((const float4*)(Wp1 + k0_)); } while (0)

#define SSTORE(buf) do {                                            \
        float* a_ = &sA[buf][lk][lr];                               \
        a_[0] = ra0.x; a_[132] = ra0.y; a_[264] = ra0.z; a_[396] = ra0.w; \
        a_[64] = ra1.x; a_[196] = ra1.y; a_[328] = ra1.z; a_[460] = ra1.w; \
        float* b_ = &sB[buf][lk][lr];                               \
        b_[0] = rb0.x; b_[132] = rb0.y; b_[264] = rb0.z; b_[396] = rb0.w; \
        b_[64] = rb1.x; b_[196] = rb1.y; b_[328] = rb1.z; b_[460] = rb1.w; } while (0)

    GLOAD(0); SSTORE(0); __syncthreads();

    for (int kb = 0; kb < 16; ++kb) {
        const int cur = kb & 1;
        if (kb < 15) GLOAD(kb + 1);
#pragma unroll
        for (int k = 0; k < 16; ++k) {
            float am[8], bn[8];
#pragma unroll
            for (int i = 0; i < 8; ++i) am[i] = sA[cur][k][ty * 8 + i];
#pragma unroll
            for (int j = 0; j < 8; ++j) bn[j] = sB[cur][k][tx * 8 + j];
#pragma unroll
            for (int i = 0; i < 8; ++i)
#pragma unroll
                for (int j = 0; j < 8; ++j)
                    acc[i][j] = fmaf(am[i], bn[j], acc[i][j]);
        }
        if (kb < 15) { SSTORE(cur ^ 1); __syncthreads(); }
    }

#pragma unroll
    for (int i = 0; i < 8; ++i) {
        size_t row = (size_t)(m0 + ty * 8 + i);
        float4 o0 = make_float4(acc[i][0], acc[i][1], acc[i][2], acc[i][3]);
        float4 o1 = make_float4(acc[i][4], acc[i][5], acc[i][6], acc[i][7]);
        *(float4*)(C + row * 1024 + n0 + tx * 8)     = o0;
        *(float4*)(C + row * 1024 + n0 + tx * 8 + 4) = o1;
    }
}

// =======================================================================
// Persistent recurrent scan (one launch per layer, K=256)
// 128 blocks: 64 per direction, each owns 4 hidden units (16 gate rows)
// thread tile: 4 gate-rows x 2 batches x K-half(128)
// =======================================================================
__global__ void __launch_bounds__(NTHREADS, 1)
scan_kernel(Params p, int layer)
{
    extern __shared__ float sm[];
    float* sWt = sm;                    // [k][16]
    float* sHb = sm + SM_HB;            // [b][276] with 4-float gap at k=128
    float* zp  = sm + SM_ZP;            // [half][16][66]
    float* hb  = sm + SM_HBUF;          // [4][65]
    float* sB  = sm + SM_B;             // [16]
    int*   sLen= (int*)(sm + SM_LEN);   // [64]

    const int tid  = threadIdx.x;
    const int dir  = blockIdx.x >> 6;
    const int j0   = (blockIdx.x & 63) << 2;
    const int rq   = tid & 3;           // gate
    const int half = (tid >> 2) & 1;    // K-half
    const int bp   = tid >> 3;          // batch pair 0..31
    const int b0   = bp << 1, b1 = b0 + 1;
    const int uj   = tid >> 6, ub = tid & 63;

    if (tid < BATCH) sLen[tid] = p.len[tid];

    const float* whh = p.w[layer * 8 + dir * 4 + 1];
    const float* bih = p.w[layer * 8 + dir * 4 + 2];
    const float* bhh = p.w[layer * 8 + dir * 4 + 3];

    for (int r = 0; r < 16; ++r) {
        int grow = ((r >> 2) << 8) + j0 + (r & 3);
        const float* wsrc = whh + (size_t)grow * HID;
        for (int k = tid; k < HID; k += NTHREADS)
            sWt[k * 16 + r] = wsrc[k];
    }
    if (tid < 16) {
        int grow = ((tid >> 2) << 8) + j0 + (tid & 3);
        sB[tid] = bih[grow] + bhh[grow];
    }
    g_h[0][dir][(tid & 63) * HID + j0 + (tid >> 6)] = 0.f;
    float creg = 0.f;

    // zin sources + per-example time-index modes (0: t, 1: (t+len)%T, 2: (t+T-len)%T)
    const float *srcA, *srcB = nullptr;
    int modeA, modeB = 0;
    if (layer == 0)      { srcA = g_zin[dir]; modeA = dir ? 1 : 0; }
    else if (dir == 0)   { srcA = g_zin[0]; modeA = 0; srcB = g_zin[1]; modeB = 2; }
    else                 { srcA = g_zin[2]; modeA = 1; srcB = g_zin[3]; modeB = 0; }

    unsigned ts = 0;
    gbar(dir, 64, ++ts);   // h zeros visible within this direction

    for (int s = 0; s < TSEQ; ++s) {
        const int par = s & 1;
        const int t = dir ? (TSEQ - 1 - s) : s;
        const float* hsrc = &g_h[par][dir][0];

        // ---- stage h into smem (gap layout: quad b*69 + kq + (kq>=32)) ----
#pragma unroll
        for (int i = 0; i < 16; ++i) {
            int f = (i << 8) + tid;
            int b = f >> 6, kq = f & 63;
            float4 v = __ldcg((const float4*)(hsrc + b * HID) + kq);
            ((float4*)sHb)[b * 69 + kq + (kq >> 5)] = v;
        }

        // ---- init accumulators from gathered zin (+bias on half 0) ----
        float a00, a10, a20, a30, a01, a11, a21, a31;
        {
            const float* src = half ? srcB : srcA;
            if (src) {
                int mode = half ? modeB : modeA;
                int lb0 = sLen[b0], lb1 = sLen[b1];
                int tA = t, tB = t;
                if (mode == 1)      { tA = t + lb0;        tB = t + lb1; }
                else if (mode == 2) { tA = t + TSEQ - lb0; tB = t + TSEQ - lb1; }
                if (tA >= TSEQ) tA -= TSEQ;
                if (tB >= TSEQ) tB -= TSEQ;
                const int col = (rq << 8) + j0;
                float4 zA = __ldg((const float4*)(src + ((size_t)tA * BATCH + b0) * 1024 + col));
                float4 zB = __ldg((const float4*)(src + ((size_t)tB * BATCH + b1) * 1024 + col));
                if (half == 0) {
                    float bi0 = sB[rq * 4 + 0], bi1 = sB[rq * 4 + 1];
                    float bi2 = sB[rq * 4 + 2], bi3 = sB[rq * 4 + 3];
                    a00 = zA.x + bi0; a10 = zA.y + bi1; a20 = zA.z + bi2; a30 = zA.w + bi3;
                    a01 = zB.x + bi0; a11 = zB.y + bi1; a21 = zB.z + bi2; a31 = zB.w + bi3;
                } else {
                    a00 = zA.x; a10 = zA.y; a20 = zA.z; a30 = zA.w;
                    a01 = zB.x; a11 = zB.y; a21 = zB.z; a31 = zB.w;
                }
            } else {
                a00 = a10 = a20 = a30 = a01 = a11 = a21 = a31 = 0.f;
            }
        }
        __syncthreads();

        // ---- recurrent GEMM: 4 rows x 2 batches over this thread's K-half ----
        {
            const float4* wq = (const float4*)sWt + (half << 9) + rq;  // k*4 + rq
            const float* h0 = sHb + b0 * 276 + half * 132;
            const float* h1 = h0 + 276;
#pragma unroll 16
            for (int kk = 0; kk < 128; ++kk) {
                float4 w = wq[kk << 2];
                float hv0 = h0[kk], hv1 = h1[kk];
                a00 = fmaf(w.x, hv0, a00); a01 = fmaf(w.x, hv1, a01);
                a10 = fmaf(w.y, hv0, a10); a11 = fmaf(w.y, hv1, a11);
                a20 = fmaf(w.z, hv0, a20); a21 = fmaf(w.z, hv1, a21);
                a30 = fmaf(w.w, hv0, a30); a31 = fmaf(w.w, hv1, a31);
            }
        }
        {
            float* zr = zp + (half * 16 + rq * 4) * 66;
            zr[0 * 66 + b0] = a00; zr[0 * 66 + b1] = a01;
            zr[1 * 66 + b0] = a10; zr[1 * 66 + b1] = a11;
            zr[2 * 66 + b0] = a20; zr[2 * 66 + b1] = a21;
            zr[3 * 66 + b0] = a30; zr[3 * 66 + b1] = a31;
        }
        __syncthreads();

        // ---- cell update: thread owns (uj, ub); c stays in register ----
        {
            float zi = zp[(0  + uj) * 66 + ub] + zp[(16 + 0  + uj) * 66 + ub];
            float zf = zp[(4  + uj) * 66 + ub] + zp[(16 + 4  + uj) * 66 + ub];
            float zg = zp[(8  + uj) * 66 + ub] + zp[(16 + 8  + uj) * 66 + ub];
            float zo = zp[(12 + uj) * 66 + ub] + zp[(16 + 12 + uj) * 66 + ub];
            float ig = sigf(zi), fg = sigf(zf), gg = tanhf(zg), og = sigf(zo);
            creg = fg * creg + ig * gg;
            float h = og * tanhf(creg);
            hb[uj * 65 + ub] = h;
            int lb = sLen[ub];
            bool trig = dir ? (t == TSEQ - lb) : (t == lb - 1);
            if (trig) {
                size_t o = OUT_LH + ((size_t)(layer * 2 + dir) * BATCH + ub) * HID + j0 + uj;
                p.out[o] = h;
                p.out[o + LHN] = creg;
            }
        }
        __syncthreads();

        // ---- write h for next step (+ history / output) ----
        {
            int j = tid & 3, b = tid >> 2;
            float hv = hb[j * 65 + b];
            g_h[par ^ 1][dir][b * HID + j0 + j] = hv;
            if (layer == 0) {
                float* hs = dir ? g_hs0b : g_hs0f;
                hs[((size_t)t * BATCH + b) * HID + j0 + j] = hv;
            } else {
                int lb = sLen[b];
                int tm = t, col = j0 + j;
                if (dir) { tm = t + lb; if (tm >= TSEQ) tm -= TSEQ; col += HID; }
                p.out[((size_t)tm * BATCH + b) * (2 * HID) + col] = (tm < lb) ? hv : 0.f;
            }
        }

        gbar(dir, 64, ++ts);
    }
}

extern "C" void kernel_launch(void* const* d_in, const int* in_sizes, int n_in,
                              void* d_out, int out_size) {
    Params P;
    P.x   = (const float*)d_in[0];
    P.len = (const int*)d_in[1];
    for (int i = 0; i < 16; ++i) P.w[i] = (const float*)d_in[2 + i];
    P.out = (float*)d_out;

    void *zp_, *hsf_, *hsb_, *sy_;
    cudaGetSymbolAddress(&zp_,  g_zin);
    cudaGetSymbolAddress(&hsf_, g_hs0f);
    cudaGetSymbolAddress(&hsb_, g_hs0b);
    cudaGetSymbolAddress(&sy_,  g_sync);
    float* z = (float*)zp_;
    const float* hsf = (const float*)hsf_;
    const float* hsb = (const float*)hsb_;
    const size_t ZN = (size_t)MTOT * 1024;

    cudaFuncSetAttribute(scan_kernel, cudaFuncAttributeMaxDynamicSharedMemorySize, SMEM_BYTES);

    dim3 gg(8, 1024);   // N-tiles x M-tiles

    // layer-0 input projections (K=256)
    gemm_k256<<<gg, 256>>>(P.x, P.w[0], 256, z);            // fwd
    gemm_k256<<<gg, 256>>>(P.x, P.w[4], 256, z + ZN);       // bwd

    cudaMemsetAsync(sy_, 0, 32);
    scan_kernel<<<NBLOCKS, NTHREADS, SMEM_BYTES>>>(P, 0);

    // layer-1 input projections: K=512 split into two K=256 halves
    gemm_k256<<<gg, 256>>>(hsf, P.w[8],        512, z);            // fwd, hsf-half
    gemm_k256<<<gg, 256>>>(hsb, P.w[8]  + 256, 512, z + ZN);       // fwd, hsb-half
    gemm_k256<<<gg, 256>>>(hsf, P.w[12],       512, z + 2 * ZN);   // bwd, hsf-half
    gemm_k256<<<gg, 256>>>(hsb, P.w[12] + 256, 512, z + 3 * ZN);   // bwd, hsb-half

    cudaMemsetAsync(sy_, 0, 32);
    scan_kernel<<<NBLOCKS, NTHREADS, SMEM_BYTES>>>(P, 1);
}

// round 6
// speedup vs baseline: 1.3372x; 1.2739x over previous
#include <cuda_runtime.h>

#define TSEQ 2048
#define BATCH 64
#define HID 256
#define NBLOCKS 128
#define NTHREADS 256
#define MTOT (TSEQ * BATCH)          // 131072 rows

#define OUT_LH 67108864UL            // T*B*2H
#define LHN    65536UL               // 4*B*H

typedef unsigned long long ull;

// ---- scratch (device statics are the sanctioned no-alloc path) ----
__device__ float g_zin[4][(size_t)MTOT * 1024];   // precomputed input projections
__device__ float g_hs0f[(size_t)MTOT * HID];
__device__ float g_hs0b[(size_t)MTOT * HID];
__device__ float g_h[2][2][BATCH * HID];          // [parity][dir][b*H + j]
__device__ unsigned g_flags[2][64];               // per-direction per-block step flags

struct Params {
    const float* __restrict__ x;
    const int*   __restrict__ len;
    const float* __restrict__ w[16];
    float*       __restrict__ out;
};

// ---------------- scan-phase shared memory layout (floats) ----------------
// sWt : [half][128][16] + 16-float inter-half gap  : 0     .. 4112
// sHb : [64][276] (4-float gap at k=128)           : 4112  .. 21776
// zp  : [2][64][20]                                : 21776 .. 24336
// hb  : [4][65]                                    : 24336 .. 24596
// sB  : [16]                                       : 24596 .. 24612
// sLen: [64] ints                                  : 24612 .. 24676
#define SM_HB   4112
#define SM_ZP   21776
#define SM_HBUF 24336
#define SM_B    24596
#define SM_LEN  24612
#define SMEM_FLOATS 24676
#define SMEM_BYTES (SMEM_FLOATS * 4)

__device__ __forceinline__ ull pck(float lo, float hi) {
    ull r;
    asm("mov.b64 %0, {%1, %2};" : "=l"(r) : "f"(lo), "f"(hi));
    return r;
}
__device__ __forceinline__ void fma2(ull& d, ull a, ull b) {
    asm("fma.rn.f32x2 %0, %1, %2, %0;" : "+l"(d) : "l"(a), "l"(b));
}
__device__ __forceinline__ ull add2(ull a, ull b) {
    ull r;
    asm("add.rn.f32x2 %0, %1, %2;" : "=l"(r) : "l"(a), "l"(b));
    return r;
}
__device__ __forceinline__ float lo2(ull v) { float a; asm("mov.b64 {%0, _}, %1;" : "=f"(a) : "l"(v)); return a; }
__device__ __forceinline__ float hi2(ull v) { float a; asm("mov.b64 {_, %0}, %1;" : "=f"(a) : "l"(v)); return a; }

__device__ __forceinline__ float sigf(float x) {
    return __fdividef(1.f, 1.f + __expf(-x));
}

// flag barrier: every block release-stores its own flag, threads 0..63 acquire-poll all
__device__ __forceinline__ void fbar(unsigned* flags, int own, unsigned ts) {
    __syncthreads();
    if (threadIdx.x == 0)
        asm volatile("st.release.gpu.global.u32 [%0], %1;" :: "l"(flags + own), "r"(ts) : "memory");
    if (threadIdx.x < 64) {
        unsigned v;
        do {
            asm volatile("ld.acquire.gpu.global.u32 %0, [%1];"
                         : "=r"(v) : "l"(flags + threadIdx.x) : "memory");
        } while (v < ts);
    }
    __syncthreads();
}

__global__ void noop_kernel() {}

// =======================================================================
// Bulk GEMM: C[M=131072,1024] = A[M,256] @ W[1024, ldw(first 256 cols)]^T
// tile 128x128, 256 threads, 8x8 per thread via fma.rn.f32x2
// =======================================================================
__global__ void __launch_bounds__(256, 2)
gemm_k256(const float* __restrict__ A, const float* __restrict__ W, int ldw,
          float* __restrict__ C)
{
    __shared__ float sA[2][16][132];
    __shared__ float sB[2][16][132];
    const int tid = threadIdx.x;
    const int m0 = blockIdx.y << 7;
    const int n0 = blockIdx.x << 7;
    const int tx = tid & 15, ty = tid >> 4;
    const int lr = tid >> 2;               // 0..63
    const int lk = (tid & 3) << 2;         // 0,4,8,12

    const float* Ap0 = A + (size_t)(m0 + lr) * 256 + lk;
    const float* Ap1 = Ap0 + (size_t)64 * 256;
    const float* Wp0 = W + (size_t)(n0 + lr) * ldw + lk;
    const float* Wp1 = Wp0 + (size_t)64 * ldw;

    ull acc2[8][4];
#pragma unroll
    for (int i = 0; i < 8; ++i)
#pragma unroll
        for (int j = 0; j < 4; ++j) acc2[i][j] = 0ull;

    float4 ra0, ra1, rb0, rb1;

#define GLOAD(kb) do { int k0_ = (kb) << 4;                         \
        ra0 = __ldg((const float4*)(Ap0 + k0_));                    \
        ra1 = __ldg((const float4*)(Ap1 + k0_));                    \
        rb0 = __ldg((const float4*)(Wp0 + k0_));                    \
        rb1 = __ldg((const float4*)(Wp1 + k0_)); } while (0)

#define SSTORE(buf) do {                                            \
        float* a_ = &sA[buf][lk][lr];                               \
        a_[0] = ra0.x; a_[132] = ra0.y; a_[264] = ra0.z; a_[396] = ra0.w; \
        a_[64] = ra1.x; a_[196] = ra1.y; a_[328] = ra1.z; a_[460] = ra1.w; \
        float* b_ = &sB[buf][lk][lr];                               \
        b_[0] = rb0.x; b_[132] = rb0.y; b_[264] = rb0.z; b_[396] = rb0.w; \
        b_[64] = rb1.x; b_[196] = rb1.y; b_[328] = rb1.z; b_[460] = rb1.w; } while (0)

    GLOAD(0); SSTORE(0); __syncthreads();

    for (int kb = 0; kb < 16; ++kb) {
        const int cur = kb & 1;
        if (kb < 15) GLOAD(kb + 1);
#pragma unroll
        for (int k = 0; k < 16; ++k) {
            float4 a0 = *(const float4*)&sA[cur][k][ty * 8];
            float4 a1 = *(const float4*)&sA[cur][k][ty * 8 + 4];
            ulonglong2 bq0 = *(const ulonglong2*)&sB[cur][k][tx * 8];
            ulonglong2 bq1 = *(const ulonglong2*)&sB[cur][k][tx * 8 + 4];
            float am[8] = {a0.x, a0.y, a0.z, a0.w, a1.x, a1.y, a1.z, a1.w};
#pragma unroll
            for (int i = 0; i < 8; ++i) {
                ull ap = pck(am[i], am[i]);
                fma2(acc2[i][0], ap, bq0.x);
                fma2(acc2[i][1], ap, bq0.y);
                fma2(acc2[i][2], ap, bq1.x);
                fma2(acc2[i][3], ap, bq1.y);
            }
        }
        if (kb < 15) { SSTORE(cur ^ 1); __syncthreads(); }
    }

#pragma unroll
    for (int i = 0; i < 8; ++i) {
        size_t row = (size_t)(m0 + ty * 8 + i);
        ulonglong2 o0; o0.x = acc2[i][0]; o0.y = acc2[i][1];
        ulonglong2 o1; o1.x = acc2[i][2]; o1.y = acc2[i][3];
        *(ulonglong2*)(C + row * 1024 + n0 + tx * 8)     = o0;
        *(ulonglong2*)(C + row * 1024 + n0 + tx * 8 + 4) = o1;
    }
}

// =======================================================================
// Persistent recurrent scan (one launch per layer, K=256, fma.rn.f32x2)
// 128 blocks: 64 per direction, each owns 4 hidden units (16 gate rows)
// thread tile: 4 gate-rows (2 row-pairs) x 2 batches x K-half(128)
// =======================================================================
__global__ void __launch_bounds__(NTHREADS, 1)
scan_kernel(Params p, int layer, unsigned tsbase)
{
    extern __shared__ float sm[];
    float* sWt = sm;                    // [half][k][16] + 16 gap
    float* sHb = sm + SM_HB;            // [b][276] with 4-float gap at k=128
    float* zp  = sm + SM_ZP;            // [half][b][20] (rows 0..15 + pad)
    float* hb  = sm + SM_HBUF;          // [4][65]
    float* sB  = sm + SM_B;             // [16]
    int*   sLen= (int*)(sm + SM_LEN);   // [64]

    const int tid  = threadIdx.x;
    const int dir  = blockIdx.x >> 6;
    const int own  = blockIdx.x & 63;
    const int j0   = own << 2;
    const int rq   = tid & 3;           // gate
    const int half = (tid >> 2) & 1;    // K-half
    const int bp   = tid >> 3;          // batch pair 0..31
    const int b0   = bp << 1, b1 = b0 + 1;
    const int uj   = tid >> 6, ub = tid & 63;
    unsigned* flags = g_flags[dir];

    if (tid < BATCH) sLen[tid] = p.len[tid];

    const float* whh = p.w[layer * 8 + dir * 4 + 1];
    const float* bih = p.w[layer * 8 + dir * 4 + 2];
    const float* bhh = p.w[layer * 8 + dir * 4 + 3];

    // weights: sWt[half][k][16] with 16-float gap between halves (bank decouple)
    for (int r = 0; r < 16; ++r) {
        int grow = ((r >> 2) << 8) + j0 + (r & 3);
        const float* wsrc = whh + (size_t)grow * HID;
        for (int k = tid; k < HID; k += NTHREADS)
            sWt[k * 16 + (k >= 128 ? 16 : 0) + r] = wsrc[k];
    }
    if (tid < 16) {
        int grow = ((tid >> 2) << 8) + j0 + (tid & 3);
        sB[tid] = bih[grow] + bhh[grow];
    }
    g_h[0][dir][(tid & 63) * HID + j0 + (tid >> 6)] = 0.f;
    float creg = 0.f;
    __syncthreads();

    // packed bias pairs (added once per step, half 0 only)
    const ull bPlo = half ? 0ull : pck(sB[rq * 4 + 0], sB[rq * 4 + 1]);
    const ull bPhi = half ? 0ull : pck(sB[rq * 4 + 2], sB[rq * 4 + 3]);

    // zin sources + per-example time modes (0: t, 1: (t+len)%T, 2: (t+T-len)%T)
    const float *srcA, *srcB = nullptr;
    int modeA, modeB = 0;
    if (layer == 0)      { srcA = g_zin[dir]; modeA = dir ? 1 : 0; }
    else if (dir == 0)   { srcA = g_zin[0]; modeA = 0; srcB = g_zin[1]; modeB = 2; }
    else                 { srcA = g_zin[2]; modeA = 1; srcB = g_zin[3]; modeB = 0; }
    const float* zsrc = half ? srcB : srcA;
    const int    zmode = half ? modeB : modeA;
    const int    zcol  = (rq << 8) + j0;

    // gather z for step s into registers (addresses depend only on t, not h)
    auto zgather = [&](int s, float4& zA, float4& zB) {
        if (!zsrc) { zA = make_float4(0,0,0,0); zB = zA; return; }
        int t = dir ? (TSEQ - 1 - s) : s;
        int tA = t, tB = t;
        int lb0 = sLen[b0], lb1 = sLen[b1];
        if (zmode == 1)      { tA = t + lb0;        tB = t + lb1; }
        else if (zmode == 2) { tA = t + TSEQ - lb0; tB = t + TSEQ - lb1; }
        if (tA >= TSEQ) tA -= TSEQ;
        if (tB >= TSEQ) tB -= TSEQ;
        zA = __ldg((const float4*)(zsrc + ((size_t)tA * BATCH + b0) * 1024 + zcol));
        zB = __ldg((const float4*)(zsrc + ((size_t)tB * BATCH + b1) * 1024 + zcol));
    };

    unsigned ts = tsbase;
    fbar(flags, own, ++ts);   // h zeros visible across the direction

    float4 znA, znB;
    zgather(0, znA, znB);     // prime the z pipeline

    for (int s = 0; s < TSEQ; ++s) {
        const int par = s & 1;
        const int t = dir ? (TSEQ - 1 - s) : s;
        const float* hsrc = &g_h[par][dir][0];

        // current-step z from prefetch; immediately issue next step's gather
        float4 zA = znA, zB = znB;
        if (s + 1 < TSEQ) zgather(s + 1, znA, znB);

        // ---- stage h into smem (gap layout: quad b*69 + kq + (kq>>5)) ----
#pragma unroll
        for (int i = 0; i < 16; ++i) {
            int f = (i << 8) + tid;
            int b = f >> 6, kq = f & 63;
            float4 v = __ldcg((const float4*)(hsrc + b * HID) + kq);
            ((float4*)sHb)[b * 69 + kq + (kq >> 5)] = v;
        }
        __syncthreads();

        // ---- recurrent GEMM: packed row-pairs x 2 batches over K-half ----
        ull c00 = pck(zA.x, zA.y), c01 = pck(zA.z, zA.w);
        ull c10 = pck(zB.x, zB.y), c11 = pck(zB.z, zB.w);
        {
            const float* wbase = sWt + half * 2064 + rq * 4;   // 2064 = 128*16 + 16
            const float* h0 = sHb + b0 * 276 + half * 132;
            const float* h1 = h0 + 276;
#pragma unroll 16
            for (int kk = 0; kk < 128; ++kk) {
                ulonglong2 w = *(const ulonglong2*)(wbase + kk * 16);
                float hv0 = h0[kk], hv1 = h1[kk];
                ull h0p = pck(hv0, hv0);
                ull h1p = pck(hv1, hv1);
                fma2(c00, w.x, h0p); fma2(c01, w.y, h0p);
                fma2(c10, w.x, h1p); fma2(c11, w.y, h1p);
            }
        }
        c00 = add2(c00, bPlo); c01 = add2(c01, bPhi);
        c10 = add2(c10, bPlo); c11 = add2(c11, bPhi);
        {
            float* zr0 = zp + (half * 64 + b0) * 20 + rq * 4;
            float* zr1 = zp + (half * 64 + b1) * 20 + rq * 4;
            *(ull*)(zr0)     = c00;  *(ull*)(zr0 + 2) = c01;
            *(ull*)(zr1)     = c10;  *(ull*)(zr1 + 2) = c11;
        }
        __syncthreads();

        // ---- cell update: thread owns (uj, ub); c stays in register ----
        {
            const float* z0 = zp + ub * 20;            // half 0
            const float* z1 = zp + (64 + ub) * 20;     // half 1
            float zi = z0[0  + uj] + z1[0  + uj];
            float zf = z0[4  + uj] + z1[4  + uj];
            float zg = z0[8  + uj] + z1[8  + uj];
            float zo = z0[12 + uj] + z1[12 + uj];
            float ig = sigf(zi), fg = sigf(zf), gg = tanhf(zg), og = sigf(zo);
            creg = fg * creg + ig * gg;
            float h = og * tanhf(creg);
            hb[uj * 65 + ub] = h;
            int lb = sLen[ub];
            bool trig = dir ? (t == TSEQ - lb) : (t == lb - 1);
            if (trig) {
                size_t o = OUT_LH + ((size_t)(layer * 2 + dir) * BATCH + ub) * HID + j0 + uj;
                p.out[o] = h;
                p.out[o + LHN] = creg;
            }
        }
        __syncthreads();

        // ---- write h for next step (+ history / output) ----
        {
            int j = tid & 3, b = tid >> 2;
            float hv = hb[j * 65 + b];
            g_h[par ^ 1][dir][b * HID + j0 + j] = hv;
            if (layer == 0) {
                float* hs = dir ? g_hs0b : g_hs0f;
                hs[((size_t)t * BATCH + b) * HID + j0 + j] = hv;
            } else {
                int lb = sLen[b];
                int tm = t, col = j0 + j;
                if (dir) { tm = t + lb; if (tm >= TSEQ) tm -= TSEQ; col += HID; }
                p.out[((size_t)tm * BATCH + b) * (2 * HID) + col] = (tm < lb) ? hv : 0.f;
            }
        }

        fbar(flags, own, ++ts);
    }
}

extern "C" void kernel_launch(void* const* d_in, const int* in_sizes, int n_in,
                              void* d_out, int out_size) {
    Params P;
    P.x   = (const float*)d_in[0];
    P.len = (const int*)d_in[1];
    for (int i = 0; i < 16; ++i) P.w[i] = (const float*)d_in[2 + i];
    P.out = (float*)d_out;

    void *zp_, *hsf_, *hsb_, *fl_;
    cudaGetSymbolAddress(&zp_,  g_zin);
    cudaGetSymbolAddress(&hsf_, g_hs0f);
    cudaGetSymbolAddress(&hsb_, g_hs0b);
    cudaGetSymbolAddress(&fl_,  g_flags);
    float* z = (float*)zp_;
    const float* hsf = (const float*)hsf_;
    const float* hsb = (const float*)hsb_;
    const size_t ZN = (size_t)MTOT * 1024;

    cudaFuncSetAttribute(scan_kernel, cudaFuncAttributeMaxDynamicSharedMemorySize, SMEM_BYTES);

    dim3 gg(8, 1024);   // N-tiles x M-tiles

    cudaMemsetAsync(fl_, 0, sizeof(g_flags));                 // launch idx 0

    // layer-0 input projections (K=256)
    gemm_k256<<<gg, 256>>>(P.x, P.w[0], 256, z);              // idx 1 (fwd)
    gemm_k256<<<gg, 256>>>(P.x, P.w[4], 256, z + ZN);         // idx 2 (bwd)

    noop_kernel<<<1, 32>>>();                                 // idx 3 (ncu alignment)
    noop_kernel<<<1, 32>>>();                                 // idx 4

    scan_kernel<<<NBLOCKS, NTHREADS, SMEM_BYTES>>>(P, 0, 0u); // idx 5 <- ncu -s 5 target

    // layer-1 input projections: K=512 split into two K=256 halves
    gemm_k256<<<gg, 256>>>(hsf, P.w[8],        512, z);            // fwd, hsf-half
    gemm_k256<<<gg, 256>>>(hsb, P.w[8]  + 256, 512, z + ZN);       // fwd, hsb-half
    gemm_k256<<<gg, 256>>>(hsf, P.w[12],       512, z + 2 * ZN);   // bwd, hsf-half
    gemm_k256<<<gg, 256>>>(hsb, P.w[12] + 256, 512, z + 3 * ZN);   // bwd, hsb-half

    scan_kernel<<<NBLOCKS, NTHREADS, SMEM_BYTES>>>(P, 1, 8192u);
}